// round 1
// baseline (speedup 1.0000x reference)
#include <cuda_runtime.h>
#include <math.h>

// Problem constants (fixed by the reference)
#define BB   4
#define TT   4
#define CC   32
#define NN   16384
#define FF   64
#define KK   9
#define PADD 4

// Tiling
#define NT       256            // n positions per block
#define WSTRIDE  68             // padded f-stride for transposed weight (16B aligned, low conflict)
#define XSTRIDE  (NT + 2*PADD)  // 264, x/coords tile width

// SMEM layout sizes (floats)
#define SW_ELEMS   (CC * KK * WSTRIDE)   // 19584
#define SX_ELEMS   (CC * XSTRIDE)        // 8448
#define SC_ELEMS   (3 * XSTRIDE)         // 792
#define SDW_ELEMS  (KK * NT)             // 2304
#define SMEM_FLOATS (SW_ELEMS + SX_ELEMS + SC_ELEMS + SDW_ELEMS)

__device__ __forceinline__ float decode_sigma(const void* p) {
    // sigma is a 1-element scalar of unknown dtype (python int 2 in the reference).
    const unsigned* w = (const unsigned*)p;
    unsigned lo = w[0];
    if (lo >= 1u && lo <= 1000000u) return (float)lo;          // int32 / int64 (LE low word)
    float f = __uint_as_float(lo);
    if (f > 1e-6f && f < 1e6f) return f;                        // float32
    return (float)(*(const double*)p);                          // float64
}

__global__ __launch_bounds__(256, 1)
void swconv1d_kernel(const float* __restrict__ x,
                     const float* __restrict__ coords,
                     const float* __restrict__ weight,
                     const void*  __restrict__ sig,
                     float* __restrict__ out)
{
    extern __shared__ float sm[];
    float* s_w  = sm;                          // [C*K][WSTRIDE] : s_w[(c*K+k)*68 + f]
    float* s_x  = s_w + SW_ELEMS;              // [C][XSTRIDE]
    float* s_c  = s_x + SX_ELEMS;              // [3][XSTRIDE]
    float* s_dw = s_c + SC_ELEMS;              // [K][NT]

    const int tid    = threadIdx.x;
    const int bt     = blockIdx.y;             // 0..15
    const int b      = bt >> 2;
    const int t      = bt & 3;
    const int n_base = blockIdx.x * NT;

    const float inv_sigma = 1.0f / decode_sigma(sig);

    // ---- stage weight[t], transposed to [ck][f] ----
    {
        const float* wt = weight + (size_t)t * FF * CC * KK;
        for (int i = tid; i < FF * CC * KK; i += 256) {
            int f  = i / (CC * KK);
            int ck = i - f * (CC * KK);
            s_w[ck * WSTRIDE + f] = wt[i];
        }
    }

    // ---- stage x tile (zero-padded) ----
    {
        const float* xb = x + (size_t)bt * CC * NN;
        for (int i = tid; i < SX_ELEMS; i += 256) {
            int c = i / XSTRIDE;
            int m = i - c * XSTRIDE;
            int n = n_base + m - PADD;
            s_x[i] = (n >= 0 && n < NN) ? xb[c * NN + n] : 0.0f;
        }
    }

    // ---- stage coords tile (zero-padded) ----
    {
        const float* cb = coords + (size_t)bt * 3 * NN;
        for (int i = tid; i < SC_ELEMS; i += 256) {
            int c = i / XSTRIDE;
            int m = i - c * XSTRIDE;
            int n = n_base + m - PADD;
            s_c[i] = (n >= 0 && n < NN) ? cb[c * NN + n] : 0.0f;
        }
    }
    __syncthreads();

    // ---- distance weights dw[k][j] = max(0, 1 - |coords(n+k-4) - coords(n)| / sigma) ----
    for (int i = tid; i < KK * NT; i += 256) {
        int k = i / NT;
        int j = i - k * NT;
        float d0 = s_c[0 * XSTRIDE + j + k] - s_c[0 * XSTRIDE + j + PADD];
        float d1 = s_c[1 * XSTRIDE + j + k] - s_c[1 * XSTRIDE + j + PADD];
        float d2 = s_c[2 * XSTRIDE + j + k] - s_c[2 * XSTRIDE + j + PADD];
        float dd = d0 * d0 + d1 * d1 + d2 * d2;
        float w  = 1.0f - sqrtf(dd) * inv_sigma;
        s_dw[i]  = w > 0.0f ? w : 0.0f;
    }
    __syncthreads();

    // ---- register-tiled compute: 8 f x 8 n per thread ----
    const int tx    = tid & 31;     // n group
    const int ty    = tid >> 5;     // f group
    const int fbase = ty * 8;
    const int n0    = tx * 8;       // local n offset within tile

    // dw for this thread's 8 n positions, all 9 taps, in registers
    float dwr[KK][8];
    #pragma unroll
    for (int k = 0; k < KK; ++k) {
        float4 a = *(const float4*)&s_dw[k * NT + n0];
        float4 c4 = *(const float4*)&s_dw[k * NT + n0 + 4];
        dwr[k][0] = a.x;  dwr[k][1] = a.y;  dwr[k][2] = a.z;  dwr[k][3] = a.w;
        dwr[k][4] = c4.x; dwr[k][5] = c4.y; dwr[k][6] = c4.z; dwr[k][7] = c4.w;
    }

    float acc[8][8];
    #pragma unroll
    for (int f = 0; f < 8; ++f)
        #pragma unroll
        for (int j = 0; j < 8; ++j) acc[f][j] = 0.0f;

    for (int c = 0; c < CC; ++c) {
        // 16-wide x window covers all taps: xr[i] = x[c][n0 + i], i in [0,16)
        float xr[16];
        #pragma unroll
        for (int q = 0; q < 4; ++q) {
            float4 v = *(const float4*)&s_x[c * XSTRIDE + n0 + q * 4];
            xr[q * 4 + 0] = v.x; xr[q * 4 + 1] = v.y;
            xr[q * 4 + 2] = v.z; xr[q * 4 + 3] = v.w;
        }
        #pragma unroll
        for (int k = 0; k < KK; ++k) {
            const float* wrow = &s_w[(c * KK + k) * WSTRIDE + fbase];
            float4 w0 = *(const float4*)&wrow[0];   // broadcast within warp
            float4 w1 = *(const float4*)&wrow[4];
            float wv[8] = {w0.x, w0.y, w0.z, w0.w, w1.x, w1.y, w1.z, w1.w};

            float ux[8];
            #pragma unroll
            for (int j = 0; j < 8; ++j)
                ux[j] = xr[j + k] * dwr[k][j];

            #pragma unroll
            for (int f = 0; f < 8; ++f)
                #pragma unroll
                for (int j = 0; j < 8; ++j)
                    acc[f][j] = fmaf(wv[f], ux[j], acc[f][j]);
        }
    }

    // ---- write out[b][t][f][n] ----
    float* ob = out + (size_t)bt * FF * NN;
    #pragma unroll
    for (int f = 0; f < 8; ++f) {
        float* orow = ob + (size_t)(fbase + f) * NN + n_base + n0;
        float4 v0 = make_float4(acc[f][0], acc[f][1], acc[f][2], acc[f][3]);
        float4 v1 = make_float4(acc[f][4], acc[f][5], acc[f][6], acc[f][7]);
        *(float4*)&orow[0] = v0;
        *(float4*)&orow[4] = v1;
    }
}

extern "C" void kernel_launch(void* const* d_in, const int* in_sizes, int n_in,
                              void* d_out, int out_size)
{
    const float* x      = (const float*)d_in[0];
    const float* coords = (const float*)d_in[1];
    const float* weight = (const float*)d_in[2];
    const void*  sig    = d_in[3];
    float*       out    = (float*)d_out;

    size_t smem_bytes = (size_t)SMEM_FLOATS * sizeof(float);   // ~124.5 KB
    cudaFuncSetAttribute(swconv1d_kernel,
                         cudaFuncAttributeMaxDynamicSharedMemorySize,
                         (int)smem_bytes);

    dim3 grid(NN / NT, BB * TT);   // (64, 16)
    swconv1d_kernel<<<grid, 256, smem_bytes>>>(x, coords, weight, sig, out);
}